// round 17
// baseline (speedup 1.0000x reference)
#include <cuda_runtime.h>
#include <cuda_fp16.h>
#include <cstdint>

#define ROWS  4096
#define INNER 1024
#define QD    1024
#define CD    768
#define HEADS 8
#define DH    128
// tau/sqrt(d) * log2(e)
#define EXP_COEF ((float)(1.5 * 0.08838834764831845 * 1.4426950408889634))

// ---------------- scratch (__device__ globals, allocation-free) ----------------
__device__ __align__(16) __half g_xh[ROWS * QD],    g_xl[ROWS * QD];
__device__ __align__(16) __half g_ch[ROWS * CD],    g_cl[ROWS * CD];
__device__ __align__(16) __half g_wqh[QD * INNER],  g_wql[QD * INNER];
__device__ __align__(16) __half g_wkh[CD * INNER],  g_wkl[CD * INNER];
__device__ __align__(16) __half g_wvh[CD * INNER],  g_wvl[CD * INNER];
__device__ __align__(16) __half g_woh[INNER * QD],  g_wol[INNER * QD];
__device__ __align__(16) __half g_Qh[ROWS * INNER];
__device__ __align__(16) __half g_Kh[ROWS * INNER];
__device__ __align__(16) __half g_Vh[ROWS * INNER];
__device__ __align__(16) __half g_Oh[ROWS * INNER], g_Ol[ROWS * INNER];

// ---------------- helpers ----------------
__device__ __forceinline__ uint32_t smem_u32(const void* p) {
    uint32_t a;
    asm("{ .reg .u64 t; cvta.to.shared.u64 t, %1; cvt.u32.u64 %0, t; }"
        : "=r"(a) : "l"(p));
    return a;
}
__device__ __forceinline__ void cpa(uint32_t dst, const void* src) {
    asm volatile("cp.async.cg.shared.global [%0], [%1], 16;" :: "r"(dst), "l"(src));
}
#define CP_COMMIT() asm volatile("cp.async.commit_group;" ::: "memory")
#define CP_WAIT1()  asm volatile("cp.async.wait_group 1;" ::: "memory")
#define CP_WAIT0()  asm volatile("cp.async.wait_group 0;" ::: "memory")

__device__ __forceinline__ void ldm_x4(uint32_t addr, uint32_t* r) {
    asm volatile("ldmatrix.sync.aligned.m8n8.x4.shared.b16 {%0,%1,%2,%3}, [%4];"
                 : "=r"(r[0]), "=r"(r[1]), "=r"(r[2]), "=r"(r[3]) : "r"(addr));
}
__device__ __forceinline__ void ldm_x4t(uint32_t addr, uint32_t* r) {
    asm volatile("ldmatrix.sync.aligned.m8n8.x4.trans.shared.b16 {%0,%1,%2,%3}, [%4];"
                 : "=r"(r[0]), "=r"(r[1]), "=r"(r[2]), "=r"(r[3]) : "r"(addr));
}
__device__ __forceinline__ void mma16816(float* c, uint32_t a0, uint32_t a1,
                                         uint32_t a2, uint32_t a3,
                                         uint32_t b0, uint32_t b1) {
    asm volatile(
        "mma.sync.aligned.m16n8k16.row.col.f32.f16.f16.f32 "
        "{%0,%1,%2,%3},{%4,%5,%6,%7},{%8,%9},{%0,%1,%2,%3};"
        : "+f"(c[0]), "+f"(c[1]), "+f"(c[2]), "+f"(c[3])
        : "r"(a0), "r"(a1), "r"(a2), "r"(a3), "r"(b0), "r"(b1));
}

// split two fp32 into packed half2 hi / lo (first arg in lower half)
__device__ __forceinline__ void split_pack(float a, float b, uint32_t& h, uint32_t& l) {
    __half ah = __float2half_rn(a);
    __half bh = __float2half_rn(b);
    __half al = __float2half_rn(a - __half2float(ah));
    __half bl = __float2half_rn(b - __half2float(bh));
    __half2 hv; hv.x = ah; hv.y = bh;
    __half2 lv; lv.x = al; lv.y = bl;
    h = *reinterpret_cast<uint32_t*>(&hv);
    l = *reinterpret_cast<uint32_t*>(&lv);
}

// ---------------- merged split: fp32 -> fp16 hi/lo, 6 segments ----------------
struct SplitJob  { const float4* src; uint32_t* hi; uint32_t* lo; int n4; };
struct SplitJobs { SplitJob j[6]; };

__global__ __launch_bounds__(256) void split_all(SplitJobs js)
{
    #pragma unroll
    for (int seg = 0; seg < 6; seg++) {
        const float4* __restrict__ src = js.j[seg].src;
        uint32_t* __restrict__ hi = js.j[seg].hi;
        uint32_t* __restrict__ lo = js.j[seg].lo;
        const int n4 = js.j[seg].n4;
        for (int i = blockIdx.x * blockDim.x + threadIdx.x; i < n4;
             i += gridDim.x * blockDim.x) {
            float4 v = src[i];
            uint32_t h0, l0, h1, l1;
            split_pack(v.x, v.y, h0, l0);
            split_pack(v.z, v.w, h1, l1);
            hi[2 * i] = h0; hi[2 * i + 1] = h1;
            lo[2 * i] = l0; lo[2 * i + 1] = l1;
        }
    }
}

// ---------------- fp16x3 GEMM tiles: 128x128, BK=32, 256 thr ----------------
#define GA_STR 80                 // bytes/row of A tile (32 fp16 + pad)
#define GB_STR 272                // bytes/row of B tile (128 fp16 + pad)
#define GA_PL  (128 * GA_STR)     // 10240
#define GB_PL  (32 * GB_STR)      // 8704
#define GBUF   (2 * GA_PL + 2 * GB_PL)
#define G_SMEM (2 * GBUF)         // 75776

// core 3-term mainloop shared by both GEMM kernels; accumulates into c[4][4][4]
__device__ __forceinline__ void gemm_body(
    uint32_t sb, const __half* Ah, const __half* Al,
    const __half* Bh, const __half* Bl,
    int N, int K, int brow, int bcol, float c[4][4][4])
{
    const int tid = threadIdx.x, w = tid >> 5, lane = tid & 31;
    const int wm = (w >> 2) * 64, wn = (w & 3) * 32;

    auto load_tile = [&](int kc, int bsel) {
        const uint32_t base = sb + bsel * GBUF;
        #pragma unroll
        for (int i = 0; i < 4; i++) {                  // A: 1024 x 16B
            int idx = tid + i * 256;
            int pl_ = idx >> 9, r = (idx >> 2) & 127, seg = idx & 3;
            const __half* s = (pl_ ? Al : Ah)
                + (size_t)(brow + r) * K + kc * 32 + seg * 8;
            cpa(base + pl_ * GA_PL + r * GA_STR + seg * 16, s);
        }
        #pragma unroll
        for (int i = 0; i < 4; i++) {                  // B: 1024 x 16B
            int idx = tid + i * 256;
            int pl_ = idx >> 9, r = (idx >> 4) & 31, seg = idx & 15;
            const __half* s = (pl_ ? Bl : Bh)
                + (size_t)(kc * 32 + r) * N + bcol + seg * 8;
            cpa(base + 2 * GA_PL + pl_ * GB_PL + r * GB_STR + seg * 16, s);
        }
    };

    const int nc = K / 32;
    load_tile(0, 0);
    CP_COMMIT();

    for (int cc = 0; cc < nc; cc++) {
        if (cc + 1 < nc) {
            load_tile(cc + 1, (cc + 1) & 1);
            CP_COMMIT();
            CP_WAIT1();
        } else {
            CP_WAIT0();
        }
        __syncthreads();

        const uint32_t ab = sb + (cc & 1) * GBUF;
        const uint32_t bb = ab + 2 * GA_PL;
        #pragma unroll
        for (int kk = 0; kk < 32; kk += 16) {
            uint32_t ah[4][4], al_[4][4];
            #pragma unroll
            for (int im = 0; im < 4; im++) {
                uint32_t adr = ab + (uint32_t)((wm + im * 16 + (lane & 15)) * GA_STR
                                               + (kk + (lane >> 4) * 8) * 2);
                ldm_x4(adr, ah[im]);
                ldm_x4(adr + GA_PL, al_[im]);
            }
            uint32_t bh[4][2], bl_[4][2];
            #pragma unroll
            for (int jg = 0; jg < 2; jg++) {
                uint32_t adr = bb
                    + (uint32_t)((kk + ((lane >> 3) & 1) * 8 + (lane & 7)) * GB_STR
                                 + (wn + jg * 16 + (lane >> 4) * 8) * 2);
                uint32_t r[4];
                ldm_x4t(adr, r);
                bh[2 * jg][0] = r[0]; bh[2 * jg][1] = r[1];
                bh[2 * jg + 1][0] = r[2]; bh[2 * jg + 1][1] = r[3];
                ldm_x4t(adr + GB_PL, r);
                bl_[2 * jg][0] = r[0]; bl_[2 * jg][1] = r[1];
                bl_[2 * jg + 1][0] = r[2]; bl_[2 * jg + 1][1] = r[3];
            }
            #pragma unroll
            for (int im = 0; im < 4; im++)
                #pragma unroll
                for (int jn = 0; jn < 4; jn++) {
                    mma16816(c[im][jn], ah[im][0], ah[im][1], ah[im][2], ah[im][3],
                             bh[jn][0], bh[jn][1]);
                    mma16816(c[im][jn], ah[im][0], ah[im][1], ah[im][2], ah[im][3],
                             bl_[jn][0], bl_[jn][1]);
                    mma16816(c[im][jn], al_[im][0], al_[im][1], al_[im][2], al_[im][3],
                             bh[jn][0], bh[jn][1]);
                }
        }
        __syncthreads();
    }
}

// ---------------- fused Q/K/V projection (blockIdx.z -> job), hi-plane out ----------------
struct PJob  { const __half *Ah, *Al, *Bh, *Bl; __half *Ch; int K; };
struct PJobs { PJob j[3]; };

__global__ __launch_bounds__(256, 2) void gemm_qkv(PJobs js)
{
    extern __shared__ char smem[];
    const uint32_t sb = smem_u32(smem);
    const PJob& J = js.j[blockIdx.z];
    const int brow = blockIdx.y * 128, bcol = blockIdx.x * 128;

    float c[4][4][4];
    #pragma unroll
    for (int i = 0; i < 4; i++)
        #pragma unroll
        for (int j = 0; j < 4; j++)
            #pragma unroll
            for (int q = 0; q < 4; q++) c[i][j][q] = 0.0f;

    gemm_body(sb, J.Ah, J.Al, J.Bh, J.Bl, INNER, J.K, brow, bcol, c);

    const int lane = threadIdx.x & 31, w = threadIdx.x >> 5;
    const int wm = (w >> 2) * 64, wn = (w & 3) * 32;
    const int g = lane >> 2, t = lane & 3;
    #pragma unroll
    for (int im = 0; im < 4; im++) {
        const int r0 = brow + wm + im * 16 + g;
        #pragma unroll
        for (int jn = 0; jn < 4; jn++) {
            const int col = bcol + wn + jn * 8 + t * 2;
            __half2 h0 = __floats2half2_rn(c[im][jn][0], c[im][jn][1]);
            __half2 h1 = __floats2half2_rn(c[im][jn][2], c[im][jn][3]);
            *(__half2*)(J.Ch + (size_t)r0 * INNER + col) = h0;
            *(__half2*)(J.Ch + (size_t)(r0 + 8) * INNER + col) = h1;
        }
    }
}

// ---------------- output projection (fp32 + bias) ----------------
__global__ __launch_bounds__(256, 2) void gemm_out(
    const __half* __restrict__ Ah, const __half* __restrict__ Al,
    const __half* __restrict__ Bh, const __half* __restrict__ Bl,
    const float* __restrict__ bias, float* __restrict__ Cf, int N, int K)
{
    extern __shared__ char smem[];
    const uint32_t sb = smem_u32(smem);
    const int brow = blockIdx.y * 128, bcol = blockIdx.x * 128;

    float c[4][4][4];
    #pragma unroll
    for (int i = 0; i < 4; i++)
        #pragma unroll
        for (int j = 0; j < 4; j++)
            #pragma unroll
            for (int q = 0; q < 4; q++) c[i][j][q] = 0.0f;

    gemm_body(sb, Ah, Al, Bh, Bl, N, K, brow, bcol, c);

    const int lane = threadIdx.x & 31, w = threadIdx.x >> 5;
    const int wm = (w >> 2) * 64, wn = (w & 3) * 32;
    const int g = lane >> 2, t = lane & 3;
    #pragma unroll
    for (int im = 0; im < 4; im++) {
        const int r0 = brow + wm + im * 16 + g;
        #pragma unroll
        for (int jn = 0; jn < 4; jn++) {
            const int col = bcol + wn + jn * 8 + t * 2;
            const float b0 = bias[col], b1 = bias[col + 1];
            float2 v0 = {c[im][jn][0] + b0, c[im][jn][1] + b1};
            float2 v1 = {c[im][jn][2] + b0, c[im][jn][3] + b1};
            *(float2*)(Cf + (size_t)r0 * N + col) = v0;
            *(float2*)(Cf + (size_t)(r0 + 8) * N + col) = v1;
        }
    }
}

// ---------------- pure-fp16 flash attention (hi planes only) ----------------
// 128 q rows per CTA (8 warps x m16), head = blockIdx.y. 64-key tiles.
// S = Qh@Kh^T, P fp16, O += Ph@Vh. O accum fp32, stored hi/lo for out-proj.
#define F_STR   272               // bytes/row (128 fp16 + pad)
#define F_QPL   (128 * F_STR)     // 34816
#define F_KPL   (64 * F_STR)      // 17408
#define F_KVBUF (2 * F_KPL)       // Kh, Vh
#define F_SMEM  (F_QPL + 2 * F_KVBUF)   // 104448 -> 2 CTAs/SM

__global__ __launch_bounds__(256, 2) void fa_mma(
    const __half* __restrict__ Qh, const __half* __restrict__ Kh,
    const __half* __restrict__ Vh,
    __half* __restrict__ Oh, __half* __restrict__ Ol)
{
    extern __shared__ char smem[];
    const uint32_t sb = smem_u32(smem);
    const int tid = threadIdx.x, w = tid >> 5, lane = tid & 31;
    const int h = blockIdx.y, q0 = blockIdx.x * 128;
    const int qm = w * 16;
    const int g = lane >> 2, t = lane & 3;

    // Q tile -> smem (hi plane), same commit group as KV0
    {
        const __half* qs = Qh + (size_t)q0 * INNER + h * DH;
        #pragma unroll
        for (int i = 0; i < 8; i++) {
            int idx = tid + i * 256;                   // 2048 x 16B
            int r = idx >> 4, seg = idx & 15;
            cpa(sb + r * F_STR + seg * 16, qs + (size_t)r * INNER + seg * 8);
        }
    }
    auto load_kv = [&](int it, int bsel) {
        const int kv0 = it * 64;
        const uint32_t base = sb + F_QPL + bsel * F_KVBUF;
        #pragma unroll
        for (int i = 0; i < 8; i++) {
            int idx = tid + i * 256;                   // 2048 x 16B
            int sub = idx >> 10, r = (idx >> 4) & 63, seg = idx & 15;
            const __half* arr = sub ? Vh : Kh;
            const __half* s = arr + (size_t)(kv0 + r) * INNER + h * DH + seg * 8;
            cpa(base + sub * F_KPL + r * F_STR + seg * 16, s);
        }
    };

    load_kv(0, 0);
    CP_COMMIT();

    float o[16][4];
    #pragma unroll
    for (int i = 0; i < 16; i++)
        #pragma unroll
        for (int q = 0; q < 4; q++) o[i][q] = 0.0f;
    float l0 = 0.0f, l1 = 0.0f;

    const int NIT = ROWS / 64;
    for (int it = 0; it < NIT; it++) {
        if (it + 1 < NIT) {
            load_kv(it + 1, (it + 1) & 1);
            CP_COMMIT();
            CP_WAIT1();
        } else {
            CP_WAIT0();
        }
        __syncthreads();

        const uint32_t kb = sb + F_QPL + (it & 1) * F_KVBUF;   // Kh plane
        const uint32_t vb = kb + F_KPL;                         // Vh plane

        // ---- S = Qh @ Kh^T : 8 n8 key chunks ----
        float s[8][4];
        #pragma unroll
        for (int j = 0; j < 8; j++)
            #pragma unroll
            for (int q = 0; q < 4; q++) s[j][q] = 0.0f;

        #pragma unroll
        for (int ks = 0; ks < 8; ks++) {               // d chunks of 16
            uint32_t qf[4];
            const uint32_t qa = sb + (uint32_t)((qm + (lane & 15)) * F_STR
                                                + (ks * 16 + (lane >> 4) * 8) * 2);
            ldm_x4(qa, qf);
            #pragma unroll
            for (int kg = 0; kg < 4; kg++) {           // key groups of 16
                const uint32_t ka = kb
                    + (uint32_t)((kg * 16 + ((lane >> 4) & 1) * 8 + (lane & 7)) * F_STR
                                 + (ks * 16 + ((lane >> 3) & 1) * 8) * 2);
                uint32_t rh[4];
                ldm_x4(ka, rh);
                mma16816(s[2*kg],   qf[0],qf[1],qf[2],qf[3], rh[0], rh[1]);
                mma16816(s[2*kg+1], qf[0],qf[1],qf[2],qf[3], rh[2], rh[3]);
            }
        }

        // ---- exp + pack P (fp16); accumulate l in fp32 ----
        uint32_t ph[4][4];
        #pragma unroll
        for (int m = 0; m < 4; m++) {
            #pragma unroll
            for (int hf = 0; hf < 2; hf++) {
                const int j = 2 * m + hf;
                const float p0 = exp2f(s[j][0] * EXP_COEF);
                const float p1 = exp2f(s[j][1] * EXP_COEF);
                const float p2 = exp2f(s[j][2] * EXP_COEF);
                const float p3 = exp2f(s[j][3] * EXP_COEF);
                l0 += p0 + p1;
                l1 += p2 + p3;
                __half2 a = __floats2half2_rn(p0, p1);
                __half2 b = __floats2half2_rn(p2, p3);
                ph[m][0 + 2 * hf] = *reinterpret_cast<uint32_t*>(&a);
                ph[m][1 + 2 * hf] = *reinterpret_cast<uint32_t*>(&b);
            }
        }

        // ---- O += P @ Vh : 16 n8 d chunks ----
        #pragma unroll
        for (int ks = 0; ks < 4; ks++) {               // key groups of 16
            #pragma unroll
            for (int dg = 0; dg < 8; dg++) {            // d groups of 16
                const uint32_t va = vb
                    + (uint32_t)((ks * 16 + ((lane >> 3) & 1) * 8 + (lane & 7)) * F_STR
                                 + (dg * 16 + ((lane >> 4) & 1) * 8) * 2);
                uint32_t rv[4];
                ldm_x4t(va, rv);
                mma16816(o[2*dg],   ph[ks][0],ph[ks][1],ph[ks][2],ph[ks][3], rv[0], rv[1]);
                mma16816(o[2*dg+1], ph[ks][0],ph[ks][1],ph[ks][2],ph[ks][3], rv[2], rv[3]);
            }
        }
        __syncthreads();
    }

    // row sums: reduce over quad (lanes sharing g)
    l0 += __shfl_xor_sync(0xffffffffu, l0, 1);
    l0 += __shfl_xor_sync(0xffffffffu, l0, 2);
    l1 += __shfl_xor_sync(0xffffffffu, l1, 1);
    l1 += __shfl_xor_sync(0xffffffffu, l1, 2);
    const float inv0 = 1.0f / l0;
    const float inv1 = 1.0f / l1;

    // normalize + store O as fp16 hi/lo (feeds 3-term out-proj)
    const int r0 = q0 + qm + g;
    #pragma unroll
    for (int dg = 0; dg < 8; dg++) {
        #pragma unroll
        for (int hf = 0; hf < 2; hf++) {
            const int j = 2 * dg + hf;
            const int col = h * DH + dg * 16 + hf * 8 + t * 2;
            uint32_t h0, l0w, h1, l1w;
            split_pack(o[j][0] * inv0, o[j][1] * inv0, h0, l0w);
            split_pack(o[j][2] * inv1, o[j][3] * inv1, h1, l1w);
            *(uint32_t*)(Oh + (size_t)r0 * INNER + col) = h0;
            *(uint32_t*)(Ol + (size_t)r0 * INNER + col) = l0w;
            *(uint32_t*)(Oh + (size_t)(r0 + 8) * INNER + col) = h1;
            *(uint32_t*)(Ol + (size_t)(r0 + 8) * INNER + col) = l1w;
        }
    }
}

// ---------------- launch ----------------
extern "C" void kernel_launch(void* const* d_in, const int* in_sizes, int n_in,
                              void* d_out, int out_size)
{
    const float* x       = (const float*)d_in[0];
    const float* context = (const float*)d_in[1];
    const float* Wq      = (const float*)d_in[2];
    const float* Wk      = (const float*)d_in[3];
    const float* Wv      = (const float*)d_in[4];
    const float* Wout    = (const float*)d_in[5];
    const float* bout    = (const float*)d_in[6];
    float* out = (float*)d_out;

    __half *xh, *xl, *ch, *cl, *wqh, *wql, *wkh, *wkl, *wvh, *wvl,
           *woh, *wol, *Qh, *Kh, *Vh, *Ohp, *Olp;
    cudaGetSymbolAddress((void**)&xh, g_xh);   cudaGetSymbolAddress((void**)&xl, g_xl);
    cudaGetSymbolAddress((void**)&ch, g_ch);   cudaGetSymbolAddress((void**)&cl, g_cl);
    cudaGetSymbolAddress((void**)&wqh, g_wqh); cudaGetSymbolAddress((void**)&wql, g_wql);
    cudaGetSymbolAddress((void**)&wkh, g_wkh); cudaGetSymbolAddress((void**)&wkl, g_wkl);
    cudaGetSymbolAddress((void**)&wvh, g_wvh); cudaGetSymbolAddress((void**)&wvl, g_wvl);
    cudaGetSymbolAddress((void**)&woh, g_woh); cudaGetSymbolAddress((void**)&wol, g_wol);
    cudaGetSymbolAddress((void**)&Qh, g_Qh);
    cudaGetSymbolAddress((void**)&Kh, g_Kh);
    cudaGetSymbolAddress((void**)&Vh, g_Vh);
    cudaGetSymbolAddress((void**)&Ohp, g_Oh);  cudaGetSymbolAddress((void**)&Olp, g_Ol);

    cudaFuncSetAttribute(gemm_qkv, cudaFuncAttributeMaxDynamicSharedMemorySize, G_SMEM);
    cudaFuncSetAttribute(gemm_out, cudaFuncAttributeMaxDynamicSharedMemorySize, G_SMEM);
    cudaFuncSetAttribute(fa_mma,   cudaFuncAttributeMaxDynamicSharedMemorySize, F_SMEM);

    // one merged split launch (fp32 -> fp16 hi/lo) for all 6 inputs
    SplitJobs js;
    js.j[0] = { (const float4*)x,       (uint32_t*)xh,  (uint32_t*)xl,  ROWS * QD / 4 };
    js.j[1] = { (const float4*)context, (uint32_t*)ch,  (uint32_t*)cl,  ROWS * CD / 4 };
    js.j[2] = { (const float4*)Wq,      (uint32_t*)wqh, (uint32_t*)wql, QD * INNER / 4 };
    js.j[3] = { (const float4*)Wk,      (uint32_t*)wkh, (uint32_t*)wkl, CD * INNER / 4 };
    js.j[4] = { (const float4*)Wv,      (uint32_t*)wvh, (uint32_t*)wvl, CD * INNER / 4 };
    js.j[5] = { (const float4*)Wout,    (uint32_t*)woh, (uint32_t*)wol, INNER * QD / 4 };
    split_all<<<1024, 256>>>(js);

    // fused Q/K/V projections (hi-plane outputs; 3-term mainloop keeps them exact)
    PJobs pj;
    pj.j[0] = { xh, xl, wqh, wql, Qh, QD };
    pj.j[1] = { ch, cl, wkh, wkl, Kh, CD };
    pj.j[2] = { ch, cl, wvh, wvl, Vh, CD };
    gemm_qkv<<<dim3(INNER / 128, ROWS / 128, 3), 256, G_SMEM>>>(pj);

    // attention (pure fp16, 2 CTAs/SM)
    fa_mma<<<dim3(ROWS / 128, HEADS), 256, F_SMEM>>>(Qh, Kh, Vh, Ohp, Olp);

    // output projection + bias (fp32 out)
    gemm_out<<<dim3(QD / 128, ROWS / 128), 256, G_SMEM>>>(
        Ohp, Olp, woh, wol, bout, out, QD, INNER);
}